// round 15
// baseline (speedup 1.0000x reference)
#include <cuda_runtime.h>
#include <cuda_fp16.h>
#include <cstdint>

// ---------------- problem constants ----------------
#define NE 8192
#define NI 2048
#define NN 10240
#define BB 16
#define TT 100

#define BCAP  128          // per-residue bucket capacity
#define SEGSZ 1024         // 8 * BCAP slots per (neuron, chunk) segment
#define NTHR  1024
#define NPBMAX 80          // max neurons per block
#define REGSZ 65664        // (4096+8) rows * 16B per half-region

#define EXP_SYN_F  ((float)0.6065306597126334)
#define DT_SYN_F   0.5f
#define EXP_NMDA_F ((float)0.9512294245007140)
#define DT_NMDA_F  0.05f
#define EXP_TAU_F  ((float)0.6065306597126334)
#define DT_TAU_F   0.5f
#define R_NMDA_F   0.4f

// unified source space: rates at row n (E: 0..8191, I: 8192..10239), aux at 10240+n
#define NU 18432
// chunks: {rE-lo, rE-hi, rI, aux-lo, aux-hi}
__constant__ int c_cbase[5] = {0, 4096, 8192, 10240, 14336};
__constant__ int c_crows[5] = {4096, 4096, 2048, 4096, 4096};

// ---------------- device scratch ----------------
__device__ __align__(256) __half g_src16[2][NU * BB];   // cross-SM data (L2-only access)
__device__ float g_ratesf[NN * BB];                     // SM-private state
__device__ float g_rec0[NN * BB];
__device__ float g_rec1[NN * BB];
__device__ float g_u[NE * BB];
__device__ float g_x[NE * BB];

__device__ int   g_bcnt[NN * 5 * 8];
__device__ short g_R[NN * 5];
__device__ __align__(256) unsigned short g_idx[(size_t)NN * 5 * SEGSZ];
__device__ float g_sclA[NN];
__device__ float g_sclB[NN];

__device__ __align__(128) int g_bar8[8 * 8];   // 8 group counters, 32B apart
__device__ int g_bar;                          // root counter
__device__ int g_sense;

// ---------------- release/acquire barrier primitives (no CCTL.IVALL) ----------------
__device__ __forceinline__ int atomAddAcqRel(int* p, int v) {
    int old;
    asm volatile("atom.acq_rel.gpu.global.add.s32 %0, [%1], %2;"
                 : "=r"(old) : "l"(p), "r"(v) : "memory");
    return old;
}
__device__ __forceinline__ void stRelease(int* p, int v) {
    asm volatile("st.release.gpu.global.s32 [%0], %1;" :: "l"(p), "r"(v) : "memory");
}
__device__ __forceinline__ int ldAcquire(const int* p) {
    int v;
    asm volatile("ld.acquire.gpu.global.s32 %0, [%1];" : "=r"(v) : "l"(p) : "memory");
    return v;
}

// slot mapping: bucket r, position p -> slot blk*64 + q*4 + s with
// q = r + 8*((p&7)>>2), s = (p&7)&3.  Gather lane q reads uint2 at (it*16+q):
// 4 consecutive u16 slots, all with row residue q&7 -> conflict-free LDS phases.
__device__ __forceinline__ void put_idx(int n, int c, int local) {
    int r = local & 7;
    int p = atomicAdd(&g_bcnt[(n * 5 + c) * 8 + r], 1);
    if (p < BCAP) {
        int blk = p >> 3, w8 = p & 7;
        int q = r + ((w8 >> 2) << 3);
        int s = w8 & 3;
        g_idx[(size_t)(n * 5 + c) * SEGSZ + blk * 64 + q * 4 + s] = (unsigned short)local;
    }
}

// ---------------- preprocessing ----------------
__global__ void k_zero() {
    int i = blockIdx.x * blockDim.x + threadIdx.x;
    if (i < NN * 5 * 8) g_bcnt[i] = 0;
    if (i < NN) { g_sclA[i] = 0.0f; g_sclB[i] = 0.0f; }
    if (i < 64) g_bar8[i] = 0;
    if (i == 0) { g_bar = 0; g_sense = 0; }
}

__global__ void k_fill_wab(const float* __restrict__ W) {
    long long i4 = (long long)blockIdx.x * blockDim.x + threadIdx.x;
    if (i4 >= (long long)NN * NN / 4) return;
    int m  = (int)(i4 / (NN / 4));
    int nb = (int)(i4 % (NN / 4)) * 4;
    float4 v = __ldg((const float4*)(W + (size_t)m * NN + nb));
    float wv[4] = {v.x, v.y, v.z, v.w};
    #pragma unroll
    for (int k = 0; k < 4; ++k) {
        float w = wv[k];
        if (w != 0.0f) {
            int n = nb + k;
            if (m < NE) {
                put_idx(n, m >> 12, m & 4095);
                g_sclA[n] = w;
            } else {
                put_idx(n, 2, m - NE);
                if (n < NE) g_sclA[n] = w; else g_sclB[n] = w;
            }
        }
    }
}

__global__ void k_fill_wstp(const float* __restrict__ W) {
    long long i4 = (long long)blockIdx.x * blockDim.x + threadIdx.x;
    if (i4 >= (long long)NE * NE / 4) return;
    int m  = (int)(i4 / (NE / 4));
    int nb = (int)(i4 % (NE / 4)) * 4;
    float4 v = __ldg((const float4*)(W + (size_t)m * NE + nb));
    float wv[4] = {v.x, v.y, v.z, v.w};
    #pragma unroll
    for (int k = 0; k < 4; ++k) {
        float w = wv[k];
        if (w != 0.0f) {
            int n = nb + k;
            put_idx(n, 3 + (m >> 12), m & 4095);
            g_sclB[n] = w;
        }
    }
}

// parallel pad: one thread per (segment, residue)
__global__ void k_pad() {
    int tid = blockIdx.x * blockDim.x + threadIdx.x;
    if (tid >= NN * 5 * 8) return;
    int seg = tid >> 3;
    int r   = tid & 7;
    int c   = seg % 5;
    const int* bc = &g_bcnt[seg * 8];
    int R = 0;
    #pragma unroll
    for (int i = 0; i < 8; ++i) R = max(R, min(bc[i], BCAP));
    int Rp = (R + 7) & ~7;
    if (r == 0) g_R[seg] = (short)Rp;
    int sent = (c == 2) ? 2048 : 4096;
    unsigned short* sp = &g_idx[(size_t)seg * SEGSZ];
    for (int p = min(bc[r], BCAP); p < Rp; ++p) {
        int blk = p >> 3, w8 = p & 7;
        int q = r + ((w8 >> 2) << 3);
        int s = w8 & 3;
        sp[blk * 64 + q * 4 + s] = (unsigned short)(sent + r);
    }
}

// ---------------- state init ----------------
__global__ void k_init(const float* __restrict__ ff, const float* __restrict__ rec) {
    int gid = blockIdx.x * blockDim.x + threadIdx.x;
    if (gid >= NN * BB) return;
    int n = gid >> 4;
    int b = gid & 15;
    float r0 = rec[(size_t)b * NN + n];
    float r1 = rec[(size_t)(BB + b) * NN + n];
    g_rec0[gid] = r0;
    g_rec1[gid] = r1;
    float f = ff[((size_t)b * TT + 0) * NN + n];
    float v = f + r0 - 1.0f;
    v = v > 0.0f ? v : 0.0f;
    g_ratesf[gid] = v;
    g_src16[0][(size_t)n * BB + b] = __float2half_rn(v);
    if (n < NE) {
        float u = 0.03f, x = 1.0f;
        u = u + 0.01f * (0.03f - u) + 0.03f * (1.0f - u) * v * 0.01f;
        x = x + 0.04f * (1.0f - x) - u * x * v * 0.01f;
        g_u[gid] = u;
        g_x[gid] = x;
        g_src16[0][(size_t)(NN + n) * BB + b] = __float2half_rn(u * x * v);
    }
}

__device__ __forceinline__ void bfly16(float2& v) {
    #pragma unroll
    for (int o = 1; o < 16; o <<= 1) {
        v.x += __shfl_xor_sync(0xffffffffu, v.x, o);
        v.y += __shfl_xor_sync(0xffffffffu, v.y, o);
    }
}

// accumulate 4 rows (one 64-slot iteration's share for this lane) into h2 accs
__device__ __forceinline__ void accum4(const char* __restrict__ hb, uint2 cur,
                                       __half2& a0, __half2& a1, __half2& a2, __half2& a3) {
    int m0 = (int)(cur.x & 0xffffu);
    int m1 = (int)(cur.x >> 16);
    int m2 = (int)(cur.y & 0xffffu);
    int m3 = (int)(cur.y >> 16);
    uint4 v;
    v = *(const uint4*)(hb + (size_t)m0 * 16);
    a0 = __hadd2(a0, *(__half2*)&v.x); a1 = __hadd2(a1, *(__half2*)&v.y);
    a2 = __hadd2(a2, *(__half2*)&v.z); a3 = __hadd2(a3, *(__half2*)&v.w);
    v = *(const uint4*)(hb + (size_t)m1 * 16);
    a0 = __hadd2(a0, *(__half2*)&v.x); a1 = __hadd2(a1, *(__half2*)&v.y);
    a2 = __hadd2(a2, *(__half2*)&v.z); a3 = __hadd2(a3, *(__half2*)&v.w);
    v = *(const uint4*)(hb + (size_t)m2 * 16);
    a0 = __hadd2(a0, *(__half2*)&v.x); a1 = __hadd2(a1, *(__half2*)&v.y);
    a2 = __hadd2(a2, *(__half2*)&v.z); a3 = __hadd2(a3, *(__half2*)&v.w);
    v = *(const uint4*)(hb + (size_t)m3 * 16);
    a0 = __hadd2(a0, *(__half2*)&v.x); a1 = __hadd2(a1, *(__half2*)&v.y);
    a2 = __hadd2(a2, *(__half2*)&v.z); a3 = __hadd2(a3, *(__half2*)&v.w);
}

// ---------------- persistent kernel ----------------
__global__ void __launch_bounds__(NTHR, 1) k_run(const float* __restrict__ ff,
                                                 float* __restrict__ out,
                                                 int nblk, int eblk) {
    extern __shared__ char smc[];
    float* __restrict__ acc = (float*)(smc + 2 * (size_t)REGSZ);
    const int tid  = threadIdx.x;
    const int wid  = tid >> 5;
    const int lane = tid & 31;
    const int q    = lane & 15;
    const int h    = lane >> 4;
    const char* __restrict__ hb = smc + (size_t)h * REGSZ;

    const int bid = blockIdx.x;
    const bool isE = bid < eblk;
    int n0, n1;
    if (isE) {
        n0 = (int)((long long)bid * NE / eblk);
        n1 = (int)((long long)(bid + 1) * NE / eblk);
    } else {
        int ib = bid - eblk, nib = nblk - eblk;
        n0 = NE + (int)((long long)ib * NI / nib);
        n1 = NE + (int)((long long)(ib + 1) * NI / nib);
    }
    const int cnt = n1 - n0;
    const int c0  = isE ? 2 : 0;    // this block's 3 chunks: c0, c0+1, c0+2

    const int grp  = bid & 7;
    const int gsz  = (nblk + 7 - grp) / 8;   // blocks with bid%8 == grp

    for (int t = 0; t < TT; ++t) {
        const int par = t & 1;

        // zero per-neuron accumulators
        for (int i = tid; i < cnt * 32; i += NTHR) acc[i] = 0.0f;

        for (int cc = 0; cc < 3; ++cc) {
            const int c = c0 + cc;
            __syncthreads();                      // consumers of prior chunk done
            {   // stage chunk c into split-half regions (L2 reads, bypass L1)
                const int rows = c_crows[c];
                const uint4* __restrict__ src =
                    (const uint4*)&g_src16[par][(size_t)c_cbase[c] * BB];
                for (int m = tid; m < rows; m += NTHR) {
                    uint4 lo = __ldcg(&src[2 * m]);
                    uint4 hi = __ldcg(&src[2 * m + 1]);
                    *(uint4*)(smc + (size_t)m * 16)         = lo;
                    *(uint4*)(smc + REGSZ + (size_t)m * 16) = hi;
                }
                if (tid < 16) {                   // 8 zero sentinel rows per region
                    uint4 z = make_uint4(0u, 0u, 0u, 0u);
                    int r = tid & 7, rg = tid >> 3;
                    *(uint4*)(smc + (size_t)rg * REGSZ + (size_t)(c_crows[c] + r) * 16) = z;
                }
            }
            __syncthreads();

            const int cls = (isE != (c == 2)) ? 1 : 0;   // 0 = class A, 1 = class B

            for (int ni = wid; ni < cnt; ni += NTHR / 32) {
                const int n = n0 + ni;
                const int Rp = (int)__ldg(&g_R[n * 5 + c]);
                if (Rp == 0) continue;
                const uint2* __restrict__ seg =
                    (const uint2*)&g_idx[(size_t)(n * 5 + c) * SEGSZ];
                float2 p0 = make_float2(0.f, 0.f), p1 = p0, p2 = p0, p3 = p0;

                const int iters = Rp >> 3;        // 64 slots per iteration
                // depth-4 rolling index prefetch (covers >500 cyc of L2/DRAM latency)
                uint2 pf0 = __ldg(&seg[q]);
                uint2 pf1 = (iters > 1) ? __ldg(&seg[1 * 16 + q]) : pf0;
                uint2 pf2 = (iters > 2) ? __ldg(&seg[2 * 16 + q]) : pf0;
                uint2 pf3 = (iters > 3) ? __ldg(&seg[3 * 16 + q]) : pf0;
                for (int it = 0; it < iters; ++it) {
                    uint2 cur = pf0;
                    pf0 = pf1; pf1 = pf2; pf2 = pf3;
                    if (it + 4 < iters) pf3 = __ldg(&seg[(it + 4) * 16 + q]);
                    __half2 a0 = __float2half2_rn(0.0f);
                    __half2 a1 = a0, a2 = a0, a3 = a0;
                    accum4(hb, cur, a0, a1, a2, a3);
                    float2 f;
                    f = __half22float2(a0); p0.x += f.x; p0.y += f.y;
                    f = __half22float2(a1); p1.x += f.x; p1.y += f.y;
                    f = __half22float2(a2); p2.x += f.x; p2.y += f.y;
                    f = __half22float2(a3); p3.x += f.x; p3.y += f.y;
                }
                bfly16(p0); bfly16(p1); bfly16(p2); bfly16(p3);
                if (q == 0) {                      // lanes 0 (h=0) and 16 (h=1)
                    float* a = &acc[(ni * 2 + cls) * 16 + h * 8];
                    a[0] += p0.x; a[1] += p0.y; a[2] += p1.x; a[3] += p1.y;
                    a[4] += p2.x; a[5] += p2.y; a[6] += p3.x; a[7] += p3.y;
                }
            }
        }
        __syncthreads();

        // ---- parallel scalar epilogue: one thread per (neuron, batch) ----
        {
            __half* __restrict__ srcn = &g_src16[par ^ 1][0];
            for (int ei = tid; ei < cnt * BB; ei += NTHR) {
                int ni = ei >> 4;
                int b  = ei & 15;
                int n  = n0 + ni;
                int e  = n * BB + b;
                float sA = g_sclA[n] * acc[(ni * 2 + 0) * 16 + b];
                float sB = g_sclB[n] * acc[(ni * 2 + 1) * 16 + b];
                float hid  = sA + sB;
                float hid2 = isE ? sB : sA;

                float r0 = g_rec0[e] * EXP_SYN_F  + hid * DT_SYN_F;
                float r1 = g_rec1[e] * EXP_NMDA_F + R_NMDA_F * hid2 * DT_NMDA_F;
                g_rec0[e] = r0;
                g_rec1[e] = r1;

                float f = __ldg(&ff[((size_t)b * TT + t) * NN + n]);
                float net = f + r0 + r1 - 1.0f;
                net = net > 0.0f ? net : 0.0f;
                float rv = g_ratesf[e] * EXP_TAU_F + net * DT_TAU_F;
                g_ratesf[e] = rv;
                out[((size_t)b * TT + t) * NN + n] = rv;
                __stcg((unsigned short*)&srcn[e],
                       (unsigned short)__half_as_ushort(__float2half_rn(rv)));
                if (isE) {
                    float u = g_u[e], x = g_x[e];
                    u = u + 0.01f * (0.03f - u) + 0.03f * (1.0f - u) * rv * 0.01f;
                    x = x + 0.04f * (1.0f - x) - u * x * rv * 0.01f;
                    g_u[e] = u;
                    g_x[e] = x;
                    __stcg((unsigned short*)&srcn[(size_t)(NN + n) * BB + b],
                           (unsigned short)__half_as_ushort(__float2half_rn(u * x * rv)));
                }
            }
        }

        // ---- grid-wide barrier: 8-way atomic tree, release/acquire ----
        __syncthreads();
        if (tid == 0) {
            int old = atomAddAcqRel(&g_bar8[grp * 8], 1);
            if (old + 1 == gsz * (t + 1)) {
                int r2 = atomAddAcqRel(&g_bar, 1);
                if (r2 + 1 == 8 * (t + 1)) {
                    stRelease(&g_sense, t + 1);
                }
            }
            while (ldAcquire(&g_sense) < t + 1) { __nanosleep(64); }
        }
        __syncthreads();
    }
}

// ---------------- launcher ----------------
extern "C" void kernel_launch(void* const* d_in, const int* in_sizes, int n_in,
                              void* d_out, int out_size) {
    const float* ff   = nullptr;
    const float* rec  = nullptr;
    const float* wab  = nullptr;
    const float* wstp = nullptr;
    for (int i = 0; i < n_in; ++i) {
        switch (in_sizes[i]) {
            case 16384000:  ff   = (const float*)d_in[i]; break;
            case 327680:    rec  = (const float*)d_in[i]; break;
            case 104857600: wab  = (const float*)d_in[i]; break;
            case 67108864:  wstp = (const float*)d_in[i]; break;
            default: break;
        }
    }
    if (!ff || !rec || !wab || !wstp) {
        ff   = (const float*)d_in[0];
        rec  = (const float*)d_in[1];
        wab  = (const float*)d_in[2];
        wstp = (const float*)d_in[3];
    }
    float* out = (float*)d_out;

    k_zero<<<(NN * 5 * 8 + 255) / 256, 256>>>();
    {
        long long tot = (long long)NN * NN / 4;
        k_fill_wab<<<(unsigned)((tot + 255) / 256), 256>>>(wab);
    }
    {
        long long tot = (long long)NE * NE / 4;
        k_fill_wstp<<<(unsigned)((tot + 255) / 256), 256>>>(wstp);
    }
    k_pad<<<(NN * 5 * 8 + 255) / 256, 256>>>();
    k_init<<<(NN * BB + 255) / 256, 256>>>(ff, rec);

    const size_t shmem = 2 * (size_t)REGSZ + (size_t)NPBMAX * 32 * sizeof(float);
    static int smem_set = 0;
    if (!smem_set) {
        cudaFuncSetAttribute(k_run, cudaFuncAttributeMaxDynamicSharedMemorySize,
                             (int)shmem);
        smem_set = 1;
    }

    int dev = 0;
    cudaGetDevice(&dev);
    int sms = 0;
    cudaDeviceGetAttribute(&sms, cudaDevAttrMultiProcessorCount, dev);
    if (sms <= 0) sms = 148;
    int nblk = sms;
    int eblk = (int)(((long long)nblk * NE + NN / 2) / NN);
    if (eblk < 1) eblk = 1;
    if (eblk > nblk - 1) eblk = nblk - 1;
    while ((NE + eblk - 1) / eblk > NPBMAX) ++eblk;
    k_run<<<nblk, NTHR, shmem>>>(ff, out, nblk, eblk);
}

// round 16
// speedup vs baseline: 1.0265x; 1.0265x over previous
#include <cuda_runtime.h>
#include <cuda_fp16.h>
#include <cstdint>

// ---------------- problem constants ----------------
#define NE 8192
#define NI 2048
#define NN 10240
#define BB 16
#define TT 100

#define BCAP  128          // per-residue bucket capacity
#define SEGSZ 1024         // 8 * BCAP slots per (neuron, chunk) segment
#define NTHR  1024
#define NPBMAX 80          // max neurons per block
#define REGSZ 65664        // (4096+8) rows * 16B per half-region

#define EXP_SYN_F  ((float)0.6065306597126334)
#define DT_SYN_F   0.5f
#define EXP_NMDA_F ((float)0.9512294245007140)
#define DT_NMDA_F  0.05f
#define EXP_TAU_F  ((float)0.6065306597126334)
#define DT_TAU_F   0.5f
#define R_NMDA_F   0.4f

// unified source space: rates at row n (E: 0..8191, I: 8192..10239), aux at 10240+n
#define NU 18432
// chunks: {rE-lo, rE-hi, rI, aux-lo, aux-hi}
__constant__ int c_cbase[5] = {0, 4096, 8192, 10240, 14336};
__constant__ int c_crows[5] = {4096, 4096, 2048, 4096, 4096};

// ---------------- device scratch ----------------
__device__ __align__(256) __half g_src16[2][NU * BB];   // cross-SM data (L2-only access)
__device__ float g_ratesf[NN * BB];                     // SM-private state
__device__ float g_rec0[NN * BB];
__device__ float g_rec1[NN * BB];
__device__ float g_u[NE * BB];
__device__ float g_x[NE * BB];

__device__ int   g_bcnt[NN * 5 * 8];
__device__ short g_R[NN * 5];
__device__ __align__(256) unsigned short g_idx[(size_t)NN * 5 * SEGSZ];
__device__ float g_sclA[NN];
__device__ float g_sclB[NN];

__device__ int g_bar;
__device__ int g_sense;

// ---------------- release/acquire barrier primitives (no CCTL.IVALL) ----------------
__device__ __forceinline__ int atomAddRelease(int* p, int v) {
    int old;
    asm volatile("atom.release.gpu.global.add.s32 %0, [%1], %2;"
                 : "=r"(old) : "l"(p), "r"(v) : "memory");
    return old;
}
__device__ __forceinline__ void stRelease(int* p, int v) {
    asm volatile("st.release.gpu.global.s32 [%0], %1;" :: "l"(p), "r"(v) : "memory");
}
__device__ __forceinline__ int ldAcquire(const int* p) {
    int v;
    asm volatile("ld.acquire.gpu.global.s32 %0, [%1];" : "=r"(v) : "l"(p) : "memory");
    return v;
}

// slot mapping: bucket r, position p -> slot blk*64 + q*4 + s with
// q = r + 8*((p&7)>>2), s = (p&7)&3.  Gather lane q reads uint2 at (it*16+q):
// 4 consecutive u16 slots, all with row residue q&7 -> conflict-free LDS phases.
__device__ __forceinline__ void put_idx(int n, int c, int local) {
    int r = local & 7;
    int p = atomicAdd(&g_bcnt[(n * 5 + c) * 8 + r], 1);
    if (p < BCAP) {
        int blk = p >> 3, w8 = p & 7;
        int q = r + ((w8 >> 2) << 3);
        int s = w8 & 3;
        g_idx[(size_t)(n * 5 + c) * SEGSZ + blk * 64 + q * 4 + s] = (unsigned short)local;
    }
}

// ---------------- preprocessing ----------------
__global__ void k_zero() {
    int i = blockIdx.x * blockDim.x + threadIdx.x;
    if (i < NN * 5 * 8) g_bcnt[i] = 0;
    if (i < NN) { g_sclA[i] = 0.0f; g_sclB[i] = 0.0f; }
    if (i == 0) { g_bar = 0; g_sense = 0; }
}

__global__ void k_fill_wab(const float* __restrict__ W) {
    long long i4 = (long long)blockIdx.x * blockDim.x + threadIdx.x;
    if (i4 >= (long long)NN * NN / 4) return;
    int m  = (int)(i4 / (NN / 4));
    int nb = (int)(i4 % (NN / 4)) * 4;
    float4 v = __ldg((const float4*)(W + (size_t)m * NN + nb));
    float wv[4] = {v.x, v.y, v.z, v.w};
    #pragma unroll
    for (int k = 0; k < 4; ++k) {
        float w = wv[k];
        if (w != 0.0f) {
            int n = nb + k;
            if (m < NE) {
                put_idx(n, m >> 12, m & 4095);
                g_sclA[n] = w;
            } else {
                put_idx(n, 2, m - NE);
                if (n < NE) g_sclA[n] = w; else g_sclB[n] = w;
            }
        }
    }
}

__global__ void k_fill_wstp(const float* __restrict__ W) {
    long long i4 = (long long)blockIdx.x * blockDim.x + threadIdx.x;
    if (i4 >= (long long)NE * NE / 4) return;
    int m  = (int)(i4 / (NE / 4));
    int nb = (int)(i4 % (NE / 4)) * 4;
    float4 v = __ldg((const float4*)(W + (size_t)m * NE + nb));
    float wv[4] = {v.x, v.y, v.z, v.w};
    #pragma unroll
    for (int k = 0; k < 4; ++k) {
        float w = wv[k];
        if (w != 0.0f) {
            int n = nb + k;
            put_idx(n, 3 + (m >> 12), m & 4095);
            g_sclB[n] = w;
        }
    }
}

// parallel pad: one thread per (segment, residue)
__global__ void k_pad() {
    int tid = blockIdx.x * blockDim.x + threadIdx.x;
    if (tid >= NN * 5 * 8) return;
    int seg = tid >> 3;
    int r   = tid & 7;
    int c   = seg % 5;
    const int* bc = &g_bcnt[seg * 8];
    int R = 0;
    #pragma unroll
    for (int i = 0; i < 8; ++i) R = max(R, min(bc[i], BCAP));
    int Rp = (R + 7) & ~7;
    if (r == 0) g_R[seg] = (short)Rp;
    int sent = (c == 2) ? 2048 : 4096;
    unsigned short* sp = &g_idx[(size_t)seg * SEGSZ];
    for (int p = min(bc[r], BCAP); p < Rp; ++p) {
        int blk = p >> 3, w8 = p & 7;
        int q = r + ((w8 >> 2) << 3);
        int s = w8 & 3;
        sp[blk * 64 + q * 4 + s] = (unsigned short)(sent + r);
    }
}

// ---------------- state init ----------------
__global__ void k_init(const float* __restrict__ ff, const float* __restrict__ rec) {
    int gid = blockIdx.x * blockDim.x + threadIdx.x;
    if (gid >= NN * BB) return;
    int n = gid >> 4;
    int b = gid & 15;
    float r0 = rec[(size_t)b * NN + n];
    float r1 = rec[(size_t)(BB + b) * NN + n];
    g_rec0[gid] = r0;
    g_rec1[gid] = r1;
    float f = ff[((size_t)b * TT + 0) * NN + n];
    float v = f + r0 - 1.0f;
    v = v > 0.0f ? v : 0.0f;
    g_ratesf[gid] = v;
    g_src16[0][(size_t)n * BB + b] = __float2half_rn(v);
    if (n < NE) {
        float u = 0.03f, x = 1.0f;
        u = u + 0.01f * (0.03f - u) + 0.03f * (1.0f - u) * v * 0.01f;
        x = x + 0.04f * (1.0f - x) - u * x * v * 0.01f;
        g_u[gid] = u;
        g_x[gid] = x;
        g_src16[0][(size_t)(NN + n) * BB + b] = __float2half_rn(u * x * v);
    }
}

__device__ __forceinline__ void bfly16(float2& v) {
    #pragma unroll
    for (int o = 1; o < 16; o <<= 1) {
        v.x += __shfl_xor_sync(0xffffffffu, v.x, o);
        v.y += __shfl_xor_sync(0xffffffffu, v.y, o);
    }
}

// accumulate 4 rows (one 64-slot iteration's share for this lane) into h2 accs
__device__ __forceinline__ void accum4(const char* __restrict__ hb, uint2 cur,
                                       __half2& a0, __half2& a1, __half2& a2, __half2& a3) {
    int m0 = (int)(cur.x & 0xffffu);
    int m1 = (int)(cur.x >> 16);
    int m2 = (int)(cur.y & 0xffffu);
    int m3 = (int)(cur.y >> 16);
    uint4 v;
    v = *(const uint4*)(hb + (size_t)m0 * 16);
    a0 = __hadd2(a0, *(__half2*)&v.x); a1 = __hadd2(a1, *(__half2*)&v.y);
    a2 = __hadd2(a2, *(__half2*)&v.z); a3 = __hadd2(a3, *(__half2*)&v.w);
    v = *(const uint4*)(hb + (size_t)m1 * 16);
    a0 = __hadd2(a0, *(__half2*)&v.x); a1 = __hadd2(a1, *(__half2*)&v.y);
    a2 = __hadd2(a2, *(__half2*)&v.z); a3 = __hadd2(a3, *(__half2*)&v.w);
    v = *(const uint4*)(hb + (size_t)m2 * 16);
    a0 = __hadd2(a0, *(__half2*)&v.x); a1 = __hadd2(a1, *(__half2*)&v.y);
    a2 = __hadd2(a2, *(__half2*)&v.z); a3 = __hadd2(a3, *(__half2*)&v.w);
    v = *(const uint4*)(hb + (size_t)m3 * 16);
    a0 = __hadd2(a0, *(__half2*)&v.x); a1 = __hadd2(a1, *(__half2*)&v.y);
    a2 = __hadd2(a2, *(__half2*)&v.z); a3 = __hadd2(a3, *(__half2*)&v.w);
}

// ---------------- persistent kernel ----------------
__global__ void __launch_bounds__(NTHR, 1) k_run(const float* __restrict__ ff,
                                                 float* __restrict__ out,
                                                 int nblk, int eblk) {
    extern __shared__ char smc[];
    float* __restrict__ acc = (float*)(smc + 2 * (size_t)REGSZ);
    const int tid  = threadIdx.x;
    const int wid  = tid >> 5;
    const int lane = tid & 31;
    const int q    = lane & 15;
    const int h    = lane >> 4;
    const char* __restrict__ hb = smc + (size_t)h * REGSZ;

    const int bid = blockIdx.x;
    const bool isE = bid < eblk;
    int n0, n1;
    if (isE) {
        n0 = (int)((long long)bid * NE / eblk);
        n1 = (int)((long long)(bid + 1) * NE / eblk);
    } else {
        int ib = bid - eblk, nib = nblk - eblk;
        n0 = NE + (int)((long long)ib * NI / nib);
        n1 = NE + (int)((long long)(ib + 1) * NI / nib);
    }
    const int cnt = n1 - n0;
    const int c0  = isE ? 2 : 0;    // this block's 3 chunks: c0, c0+1, c0+2

    for (int t = 0; t < TT; ++t) {
        const int par = t & 1;

        // zero per-neuron accumulators
        for (int i = tid; i < cnt * 32; i += NTHR) acc[i] = 0.0f;

        for (int cc = 0; cc < 3; ++cc) {
            const int c = c0 + cc;
            __syncthreads();                      // consumers of prior chunk done
            {   // stage chunk c into split-half regions (L2 reads, bypass L1)
                const int rows = c_crows[c];
                const uint4* __restrict__ src =
                    (const uint4*)&g_src16[par][(size_t)c_cbase[c] * BB];
                for (int m = tid; m < rows; m += NTHR) {
                    uint4 lo = __ldcg(&src[2 * m]);
                    uint4 hi = __ldcg(&src[2 * m + 1]);
                    *(uint4*)(smc + (size_t)m * 16)         = lo;
                    *(uint4*)(smc + REGSZ + (size_t)m * 16) = hi;
                }
                if (tid < 16) {                   // 8 zero sentinel rows per region
                    uint4 z = make_uint4(0u, 0u, 0u, 0u);
                    int r = tid & 7, rg = tid >> 3;
                    *(uint4*)(smc + (size_t)rg * REGSZ + (size_t)(c_crows[c] + r) * 16) = z;
                }
            }
            __syncthreads();

            const int cls = (isE != (c == 2)) ? 1 : 0;   // 0 = class A, 1 = class B

            for (int ni = wid; ni < cnt; ni += NTHR / 32) {
                const int n = n0 + ni;
                const int Rp = (int)__ldg(&g_R[n * 5 + c]);
                if (Rp == 0) continue;
                const uint2* __restrict__ seg =
                    (const uint2*)&g_idx[(size_t)(n * 5 + c) * SEGSZ];
                float2 p0 = make_float2(0.f, 0.f), p1 = p0, p2 = p0, p3 = p0;

                const int iters = Rp >> 3;        // 64 slots per iteration
                // depth-4 rolling index prefetch (covers >500 cyc of L2/DRAM latency)
                uint2 pf0 = __ldg(&seg[q]);
                uint2 pf1 = (iters > 1) ? __ldg(&seg[1 * 16 + q]) : pf0;
                uint2 pf2 = (iters > 2) ? __ldg(&seg[2 * 16 + q]) : pf0;
                uint2 pf3 = (iters > 3) ? __ldg(&seg[3 * 16 + q]) : pf0;
                for (int it = 0; it < iters; ++it) {
                    uint2 cur = pf0;
                    pf0 = pf1; pf1 = pf2; pf2 = pf3;
                    if (it + 4 < iters) pf3 = __ldg(&seg[(it + 4) * 16 + q]);
                    __half2 a0 = __float2half2_rn(0.0f);
                    __half2 a1 = a0, a2 = a0, a3 = a0;
                    accum4(hb, cur, a0, a1, a2, a3);
                    float2 f;
                    f = __half22float2(a0); p0.x += f.x; p0.y += f.y;
                    f = __half22float2(a1); p1.x += f.x; p1.y += f.y;
                    f = __half22float2(a2); p2.x += f.x; p2.y += f.y;
                    f = __half22float2(a3); p3.x += f.x; p3.y += f.y;
                }
                bfly16(p0); bfly16(p1); bfly16(p2); bfly16(p3);
                if (q == 0) {                      // lanes 0 (h=0) and 16 (h=1)
                    float* a = &acc[(ni * 2 + cls) * 16 + h * 8];
                    a[0] += p0.x; a[1] += p0.y; a[2] += p1.x; a[3] += p1.y;
                    a[4] += p2.x; a[5] += p2.y; a[6] += p3.x; a[7] += p3.y;
                }
            }
        }
        __syncthreads();

        // ---- parallel scalar epilogue: one thread per (neuron, batch) ----
        {
            __half* __restrict__ srcn = &g_src16[par ^ 1][0];
            for (int ei = tid; ei < cnt * BB; ei += NTHR) {
                int ni = ei >> 4;
                int b  = ei & 15;
                int n  = n0 + ni;
                int e  = n * BB + b;
                float sA = g_sclA[n] * acc[(ni * 2 + 0) * 16 + b];
                float sB = g_sclB[n] * acc[(ni * 2 + 1) * 16 + b];
                float hid  = sA + sB;
                float hid2 = isE ? sB : sA;

                float r0 = g_rec0[e] * EXP_SYN_F  + hid * DT_SYN_F;
                float r1 = g_rec1[e] * EXP_NMDA_F + R_NMDA_F * hid2 * DT_NMDA_F;
                g_rec0[e] = r0;
                g_rec1[e] = r1;

                float f = __ldg(&ff[((size_t)b * TT + t) * NN + n]);
                float net = f + r0 + r1 - 1.0f;
                net = net > 0.0f ? net : 0.0f;
                float rv = g_ratesf[e] * EXP_TAU_F + net * DT_TAU_F;
                g_ratesf[e] = rv;
                out[((size_t)b * TT + t) * NN + n] = rv;
                __stcg((unsigned short*)&srcn[e],
                       (unsigned short)__half_as_ushort(__float2half_rn(rv)));
                if (isE) {
                    float u = g_u[e], x = g_x[e];
                    u = u + 0.01f * (0.03f - u) + 0.03f * (1.0f - u) * rv * 0.01f;
                    x = x + 0.04f * (1.0f - x) - u * x * rv * 0.01f;
                    g_u[e] = u;
                    g_x[e] = x;
                    __stcg((unsigned short*)&srcn[(size_t)(NN + n) * BB + b],
                           (unsigned short)__half_as_ushort(__float2half_rn(u * x * rv)));
                }
            }
        }

        // ---- grid-wide barrier: flat release/acquire (no CCTL.IVALL) ----
        __syncthreads();
        if (tid == 0) {
            int arrived = atomAddRelease(&g_bar, 1) + 1;
            if (arrived == nblk * (t + 1)) {
                stRelease(&g_sense, t + 1);
            } else {
                while (ldAcquire(&g_sense) < t + 1) { __nanosleep(64); }
            }
        }
        __syncthreads();
    }
}

// ---------------- launcher ----------------
extern "C" void kernel_launch(void* const* d_in, const int* in_sizes, int n_in,
                              void* d_out, int out_size) {
    const float* ff   = nullptr;
    const float* rec  = nullptr;
    const float* wab  = nullptr;
    const float* wstp = nullptr;
    for (int i = 0; i < n_in; ++i) {
        switch (in_sizes[i]) {
            case 16384000:  ff   = (const float*)d_in[i]; break;
            case 327680:    rec  = (const float*)d_in[i]; break;
            case 104857600: wab  = (const float*)d_in[i]; break;
            case 67108864:  wstp = (const float*)d_in[i]; break;
            default: break;
        }
    }
    if (!ff || !rec || !wab || !wstp) {
        ff   = (const float*)d_in[0];
        rec  = (const float*)d_in[1];
        wab  = (const float*)d_in[2];
        wstp = (const float*)d_in[3];
    }
    float* out = (float*)d_out;

    k_zero<<<(NN * 5 * 8 + 255) / 256, 256>>>();
    {
        long long tot = (long long)NN * NN / 4;
        k_fill_wab<<<(unsigned)((tot + 255) / 256), 256>>>(wab);
    }
    {
        long long tot = (long long)NE * NE / 4;
        k_fill_wstp<<<(unsigned)((tot + 255) / 256), 256>>>(wstp);
    }
    k_pad<<<(NN * 5 * 8 + 255) / 256, 256>>>();
    k_init<<<(NN * BB + 255) / 256, 256>>>(ff, rec);

    const size_t shmem = 2 * (size_t)REGSZ + (size_t)NPBMAX * 32 * sizeof(float);
    static int smem_set = 0;
    if (!smem_set) {
        cudaFuncSetAttribute(k_run, cudaFuncAttributeMaxDynamicSharedMemorySize,
                             (int)shmem);
        smem_set = 1;
    }

    int dev = 0;
    cudaGetDevice(&dev);
    int sms = 0;
    cudaDeviceGetAttribute(&sms, cudaDevAttrMultiProcessorCount, dev);
    if (sms <= 0) sms = 148;
    int nblk = sms;
    int eblk = (int)(((long long)nblk * NE + NN / 2) / NN);
    if (eblk < 1) eblk = 1;
    if (eblk > nblk - 1) eblk = nblk - 1;
    while ((NE + eblk - 1) / eblk > NPBMAX) ++eblk;
    k_run<<<nblk, NTHR, shmem>>>(ff, out, nblk, eblk);
}

// round 17
// speedup vs baseline: 1.0278x; 1.0012x over previous
#include <cuda_runtime.h>
#include <cuda_fp16.h>
#include <cstdint>

// ---------------- problem constants ----------------
#define NE 8192
#define NI 2048
#define NN 10240
#define BB 16
#define TT 100

#define BCAP  128          // per-residue bucket capacity
#define SEGSZ 1024         // 8 * BCAP slots per (neuron, chunk) segment
#define NTHR  1024
#define NPBMAX 80          // max neurons per block
#define BUFROWS 6152       // 6144 data rows + 8 zero sentinel rows
#define REGSZ (BUFROWS * 16)   // bytes per half-region (98432)

#define EXP_SYN_F  ((float)0.6065306597126334)
#define DT_SYN_F   0.5f
#define EXP_NMDA_F ((float)0.9512294245007140)
#define DT_NMDA_F  0.05f
#define EXP_TAU_F  ((float)0.6065306597126334)
#define DT_TAU_F   0.5f
#define R_NMDA_F   0.4f

// unified source space: rates at row n (E: 0..8191, I: 8192..10239), aux at 10240+n
#define NU 18432
// chunks: {rE-lo, rE-hi, rI, aux-lo, aux-hi}
__constant__ int c_cbase[5] = {0, 4096, 8192, 10240, 14336};

// ---------------- device scratch ----------------
__device__ __align__(256) __half g_src16[2][NU * BB];   // cross-SM data (L2-only access)
__device__ float g_ratesf[NN * BB];                     // SM-private state
__device__ float g_rec0[NN * BB];
__device__ float g_rec1[NN * BB];
__device__ float g_u[NE * BB];
__device__ float g_x[NE * BB];

__device__ int   g_bcnt[NN * 5 * 8];
__device__ short g_R[NN * 5];
__device__ __align__(256) unsigned short g_idx[(size_t)NN * 5 * SEGSZ];
__device__ float g_sclA[NN];
__device__ float g_sclB[NN];

__device__ int g_bar;
__device__ int g_sense;

// ---------------- release/acquire barrier primitives (no CCTL.IVALL) ----------------
__device__ __forceinline__ int atomAddRelease(int* p, int v) {
    int old;
    asm volatile("atom.release.gpu.global.add.s32 %0, [%1], %2;"
                 : "=r"(old) : "l"(p), "r"(v) : "memory");
    return old;
}
__device__ __forceinline__ void stRelease(int* p, int v) {
    asm volatile("st.release.gpu.global.s32 [%0], %1;" :: "l"(p), "r"(v) : "memory");
}
__device__ __forceinline__ int ldAcquire(const int* p) {
    int v;
    asm volatile("ld.acquire.gpu.global.s32 %0, [%1];" : "=r"(v) : "l"(p) : "memory");
    return v;
}

// slot mapping: bucket r, position p -> slot blk*64 + q*4 + s with
// q = r + 8*((p&7)>>2), s = (p&7)&3.  Gather lane q reads uint2 at (it*16+q):
// 4 consecutive u16 slots, all with row residue q&7 -> conflict-free LDS phases.
__device__ __forceinline__ void put_idx(int n, int c, int local) {
    int r = local & 7;
    int p = atomicAdd(&g_bcnt[(n * 5 + c) * 8 + r], 1);
    if (p < BCAP) {
        int blk = p >> 3, w8 = p & 7;
        int q = r + ((w8 >> 2) << 3);
        int s = w8 & 3;
        g_idx[(size_t)(n * 5 + c) * SEGSZ + blk * 64 + q * 4 + s] = (unsigned short)local;
    }
}

// ---------------- preprocessing ----------------
__global__ void k_zero() {
    int i = blockIdx.x * blockDim.x + threadIdx.x;
    if (i < NN * 5 * 8) g_bcnt[i] = 0;
    if (i < NN) { g_sclA[i] = 0.0f; g_sclB[i] = 0.0f; }
    if (i == 0) { g_bar = 0; g_sense = 0; }
}

__global__ void k_fill_wab(const float* __restrict__ W) {
    long long i4 = (long long)blockIdx.x * blockDim.x + threadIdx.x;
    if (i4 >= (long long)NN * NN / 4) return;
    int m  = (int)(i4 / (NN / 4));
    int nb = (int)(i4 % (NN / 4)) * 4;
    float4 v = __ldg((const float4*)(W + (size_t)m * NN + nb));
    float wv[4] = {v.x, v.y, v.z, v.w};
    #pragma unroll
    for (int k = 0; k < 4; ++k) {
        float w = wv[k];
        if (w != 0.0f) {
            int n = nb + k;
            if (m < NE) {
                put_idx(n, m >> 12, m & 4095);
                g_sclA[n] = w;
            } else {
                put_idx(n, 2, m - NE);
                if (n < NE) g_sclA[n] = w; else g_sclB[n] = w;
            }
        }
    }
}

__global__ void k_fill_wstp(const float* __restrict__ W) {
    long long i4 = (long long)blockIdx.x * blockDim.x + threadIdx.x;
    if (i4 >= (long long)NE * NE / 4) return;
    int m  = (int)(i4 / (NE / 4));
    int nb = (int)(i4 % (NE / 4)) * 4;
    float4 v = __ldg((const float4*)(W + (size_t)m * NE + nb));
    float wv[4] = {v.x, v.y, v.z, v.w};
    #pragma unroll
    for (int k = 0; k < 4; ++k) {
        float w = wv[k];
        if (w != 0.0f) {
            int n = nb + k;
            put_idx(n, 3 + (m >> 12), m & 4095);
            g_sclB[n] = w;
        }
    }
}

// parallel pad: one thread per (segment, residue)
// sentinels: chunk 2 (rI, staged at buffer base 0) -> row 6144+r (zeroed rows)
//            chunks 0,1,3,4 (4096-row chunks)      -> local 4096+r
//            (lo-chunks staged at base 2048: 2048+4096+r = 6144+r -> same zero rows;
//             hi-chunks staged at base 0: rows 4096+r zeroed in phase 2)
__global__ void k_pad() {
    int tid = blockIdx.x * blockDim.x + threadIdx.x;
    if (tid >= NN * 5 * 8) return;
    int seg = tid >> 3;
    int r   = tid & 7;
    int c   = seg % 5;
    const int* bc = &g_bcnt[seg * 8];
    int R = 0;
    #pragma unroll
    for (int i = 0; i < 8; ++i) R = max(R, min(bc[i], BCAP));
    int Rp = (R + 7) & ~7;
    if (r == 0) g_R[seg] = (short)Rp;
    int sent = (c == 2) ? 6144 : 4096;
    unsigned short* sp = &g_idx[(size_t)seg * SEGSZ];
    for (int p = min(bc[r], BCAP); p < Rp; ++p) {
        int blk = p >> 3, w8 = p & 7;
        int q = r + ((w8 >> 2) << 3);
        int s = w8 & 3;
        sp[blk * 64 + q * 4 + s] = (unsigned short)(sent + r);
    }
}

// ---------------- state init ----------------
__global__ void k_init(const float* __restrict__ ff, const float* __restrict__ rec) {
    int gid = blockIdx.x * blockDim.x + threadIdx.x;
    if (gid >= NN * BB) return;
    int n = gid >> 4;
    int b = gid & 15;
    float r0 = rec[(size_t)b * NN + n];
    float r1 = rec[(size_t)(BB + b) * NN + n];
    g_rec0[gid] = r0;
    g_rec1[gid] = r1;
    float f = ff[((size_t)b * TT + 0) * NN + n];
    float v = f + r0 - 1.0f;
    v = v > 0.0f ? v : 0.0f;
    g_ratesf[gid] = v;
    g_src16[0][(size_t)n * BB + b] = __float2half_rn(v);
    if (n < NE) {
        float u = 0.03f, x = 1.0f;
        u = u + 0.01f * (0.03f - u) + 0.03f * (1.0f - u) * v * 0.01f;
        x = x + 0.04f * (1.0f - x) - u * x * v * 0.01f;
        g_u[gid] = u;
        g_x[gid] = x;
        g_src16[0][(size_t)(NN + n) * BB + b] = __float2half_rn(u * x * v);
    }
}

__device__ __forceinline__ void bfly16(float2& v) {
    #pragma unroll
    for (int o = 1; o < 16; o <<= 1) {
        v.x += __shfl_xor_sync(0xffffffffu, v.x, o);
        v.y += __shfl_xor_sync(0xffffffffu, v.y, o);
    }
}

// accumulate 4 rows (one 64-slot iteration's share for this lane) into h2 accs
__device__ __forceinline__ void accum4(const char* __restrict__ hb, uint2 cur,
                                       __half2& a0, __half2& a1, __half2& a2, __half2& a3) {
    int m0 = (int)(cur.x & 0xffffu);
    int m1 = (int)(cur.x >> 16);
    int m2 = (int)(cur.y & 0xffffu);
    int m3 = (int)(cur.y >> 16);
    uint4 v;
    v = *(const uint4*)(hb + (size_t)m0 * 16);
    a0 = __hadd2(a0, *(__half2*)&v.x); a1 = __hadd2(a1, *(__half2*)&v.y);
    a2 = __hadd2(a2, *(__half2*)&v.z); a3 = __hadd2(a3, *(__half2*)&v.w);
    v = *(const uint4*)(hb + (size_t)m1 * 16);
    a0 = __hadd2(a0, *(__half2*)&v.x); a1 = __hadd2(a1, *(__half2*)&v.y);
    a2 = __hadd2(a2, *(__half2*)&v.z); a3 = __hadd2(a3, *(__half2*)&v.w);
    v = *(const uint4*)(hb + (size_t)m2 * 16);
    a0 = __hadd2(a0, *(__half2*)&v.x); a1 = __hadd2(a1, *(__half2*)&v.y);
    a2 = __hadd2(a2, *(__half2*)&v.z); a3 = __hadd2(a3, *(__half2*)&v.w);
    v = *(const uint4*)(hb + (size_t)m3 * 16);
    a0 = __hadd2(a0, *(__half2*)&v.x); a1 = __hadd2(a1, *(__half2*)&v.y);
    a2 = __hadd2(a2, *(__half2*)&v.z); a3 = __hadd2(a3, *(__half2*)&v.w);
}

// gather one chunk's segment for the warp's neurons, merging into smem acc
__device__ __forceinline__ void gather_chunk(
    int n0, int cnt, int c, int cls, const char* __restrict__ hbase,
    float* __restrict__ acc, int wid, int q, int h)
{
    for (int ni = wid; ni < cnt; ni += NTHR / 32) {
        const int n = n0 + ni;
        const int Rp = (int)__ldg(&g_R[n * 5 + c]);
        if (Rp == 0) continue;
        const uint2* __restrict__ seg =
            (const uint2*)&g_idx[(size_t)(n * 5 + c) * SEGSZ];
        float2 p0 = make_float2(0.f, 0.f), p1 = p0, p2 = p0, p3 = p0;

        const int iters = Rp >> 3;        // 64 slots per iteration
        // depth-4 rolling index prefetch (covers >500 cyc of L2/DRAM latency)
        uint2 pf0 = __ldg(&seg[q]);
        uint2 pf1 = (iters > 1) ? __ldg(&seg[1 * 16 + q]) : pf0;
        uint2 pf2 = (iters > 2) ? __ldg(&seg[2 * 16 + q]) : pf0;
        uint2 pf3 = (iters > 3) ? __ldg(&seg[3 * 16 + q]) : pf0;
        for (int it = 0; it < iters; ++it) {
            uint2 cur = pf0;
            pf0 = pf1; pf1 = pf2; pf2 = pf3;
            if (it + 4 < iters) pf3 = __ldg(&seg[(it + 4) * 16 + q]);
            __half2 a0 = __float2half2_rn(0.0f);
            __half2 a1 = a0, a2 = a0, a3 = a0;
            accum4(hbase, cur, a0, a1, a2, a3);
            float2 f;
            f = __half22float2(a0); p0.x += f.x; p0.y += f.y;
            f = __half22float2(a1); p1.x += f.x; p1.y += f.y;
            f = __half22float2(a2); p2.x += f.x; p2.y += f.y;
            f = __half22float2(a3); p3.x += f.x; p3.y += f.y;
        }
        bfly16(p0); bfly16(p1); bfly16(p2); bfly16(p3);
        if (q == 0) {                      // lanes 0 (h=0) and 16 (h=1)
            float* a = &acc[(ni * 2 + cls) * 16 + h * 8];
            a[0] += p0.x; a[1] += p0.y; a[2] += p1.x; a[3] += p1.y;
            a[4] += p2.x; a[5] += p2.y; a[6] += p3.x; a[7] += p3.y;
        }
    }
}

// ---------------- persistent kernel ----------------
__global__ void __launch_bounds__(NTHR, 1) k_run(const float* __restrict__ ff,
                                                 float* __restrict__ out,
                                                 int nblk, int eblk) {
    extern __shared__ char smc[];
    float* __restrict__ acc = (float*)(smc + 2 * (size_t)REGSZ);
    const int tid  = threadIdx.x;
    const int wid  = tid >> 5;
    const int lane = tid & 31;
    const int q    = lane & 15;
    const int h    = lane >> 4;
    const char* __restrict__ hb = smc + (size_t)h * REGSZ;

    const int bid = blockIdx.x;
    const bool isE = bid < eblk;
    int n0, n1;
    if (isE) {
        n0 = (int)((long long)bid * NE / eblk);
        n1 = (int)((long long)(bid + 1) * NE / eblk);
    } else {
        int ib = bid - eblk, nib = nblk - eblk;
        n0 = NE + (int)((long long)ib * NI / nib);
        n1 = NE + (int)((long long)(ib + 1) * NI / nib);
    }
    const int cnt = n1 - n0;
    const int cLo = isE ? 3 : 0;     // lo 4096-row chunk (staged at base 2048)
    const int cHi = isE ? 4 : 1;     // hi 4096-row chunk (staged at base 0)
    // class of chunk: cls = (isE != (c==2)) ? 1 : 0
    const int clsI  = isE ? 0 : 1;   // chunk 2
    const int clsLH = isE ? 1 : 0;   // chunks lo/hi

    for (int t = 0; t < TT; ++t) {
        const int par = t & 1;

        // zero per-neuron accumulators
        for (int i = tid; i < cnt * 32; i += NTHR) acc[i] = 0.0f;
        __syncthreads();                      // prior step's gather/epilogue done

        // ---- phase 1: stage rI (rows 0-2047) + lo chunk (rows 2048-6143) ----
        {
            const __half* srcAll = &g_src16[par][0];
            const uint4* __restrict__ srcI  =
                (const uint4*)(srcAll + (size_t)c_cbase[2] * BB);
            const uint4* __restrict__ srcLo =
                (const uint4*)(srcAll + (size_t)c_cbase[cLo] * BB);
            for (int m = tid; m < 6144; m += NTHR) {
                const uint4* s = (m < 2048) ? &srcI[2 * m] : &srcLo[2 * (m - 2048)];
                uint4 lo4 = __ldcg(&s[0]);
                uint4 hi4 = __ldcg(&s[1]);
                *(uint4*)(smc + (size_t)m * 16)         = lo4;
                *(uint4*)(smc + REGSZ + (size_t)m * 16) = hi4;
            }
            if (tid < 16) {                   // zero sentinel rows 6144-6151
                uint4 z = make_uint4(0u, 0u, 0u, 0u);
                int r = tid & 7, rg = tid >> 3;
                *(uint4*)(smc + (size_t)rg * REGSZ + (size_t)(6144 + r) * 16) = z;
            }
        }
        __syncthreads();

        // ---- gather phase-1 chunks ----
        gather_chunk(n0, cnt, 2,   clsI,  hb,                       acc, wid, q, h);
        gather_chunk(n0, cnt, cLo, clsLH, hb + (size_t)2048 * 16,   acc, wid, q, h);
        __syncthreads();

        // ---- phase 2: stage hi chunk at rows 0-4095, zero rows 4096-4103 ----
        {
            const uint4* __restrict__ srcHi =
                (const uint4*)(&g_src16[par][0] + (size_t)c_cbase[cHi] * BB);
            for (int m = tid; m < 4096; m += NTHR) {
                uint4 lo4 = __ldcg(&srcHi[2 * m]);
                uint4 hi4 = __ldcg(&srcHi[2 * m + 1]);
                *(uint4*)(smc + (size_t)m * 16)         = lo4;
                *(uint4*)(smc + REGSZ + (size_t)m * 16) = hi4;
            }
            if (tid < 16) {                   // zero sentinel rows 4096-4103
                uint4 z = make_uint4(0u, 0u, 0u, 0u);
                int r = tid & 7, rg = tid >> 3;
                *(uint4*)(smc + (size_t)rg * REGSZ + (size_t)(4096 + r) * 16) = z;
            }
        }
        __syncthreads();

        // ---- gather phase-2 chunk ----
        gather_chunk(n0, cnt, cHi, clsLH, hb, acc, wid, q, h);
        __syncthreads();

        // ---- parallel scalar epilogue: one thread per (neuron, batch) ----
        {
            __half* __restrict__ srcn = &g_src16[par ^ 1][0];
            for (int ei = tid; ei < cnt * BB; ei += NTHR) {
                int ni = ei >> 4;
                int b  = ei & 15;
                int n  = n0 + ni;
                int e  = n * BB + b;
                float sA = g_sclA[n] * acc[(ni * 2 + 0) * 16 + b];
                float sB = g_sclB[n] * acc[(ni * 2 + 1) * 16 + b];
                float hid  = sA + sB;
                float hid2 = isE ? sB : sA;

                float r0 = g_rec0[e] * EXP_SYN_F  + hid * DT_SYN_F;
                float r1 = g_rec1[e] * EXP_NMDA_F + R_NMDA_F * hid2 * DT_NMDA_F;
                g_rec0[e] = r0;
                g_rec1[e] = r1;

                float f = __ldg(&ff[((size_t)b * TT + t) * NN + n]);
                float net = f + r0 + r1 - 1.0f;
                net = net > 0.0f ? net : 0.0f;
                float rv = g_ratesf[e] * EXP_TAU_F + net * DT_TAU_F;
                g_ratesf[e] = rv;
                out[((size_t)b * TT + t) * NN + n] = rv;
                __stcg((unsigned short*)&srcn[e],
                       (unsigned short)__half_as_ushort(__float2half_rn(rv)));
                if (isE) {
                    float u = g_u[e], x = g_x[e];
                    u = u + 0.01f * (0.03f - u) + 0.03f * (1.0f - u) * rv * 0.01f;
                    x = x + 0.04f * (1.0f - x) - u * x * rv * 0.01f;
                    g_u[e] = u;
                    g_x[e] = x;
                    __stcg((unsigned short*)&srcn[(size_t)(NN + n) * BB + b],
                           (unsigned short)__half_as_ushort(__float2half_rn(u * x * rv)));
                }
            }
        }

        // ---- grid-wide barrier: flat release/acquire (no CCTL.IVALL) ----
        __syncthreads();
        if (tid == 0) {
            int arrived = atomAddRelease(&g_bar, 1) + 1;
            if (arrived == nblk * (t + 1)) {
                stRelease(&g_sense, t + 1);
            } else {
                while (ldAcquire(&g_sense) < t + 1) { __nanosleep(64); }
            }
        }
        __syncthreads();
    }
}

// ---------------- launcher ----------------
extern "C" void kernel_launch(void* const* d_in, const int* in_sizes, int n_in,
                              void* d_out, int out_size) {
    const float* ff   = nullptr;
    const float* rec  = nullptr;
    const float* wab  = nullptr;
    const float* wstp = nullptr;
    for (int i = 0; i < n_in; ++i) {
        switch (in_sizes[i]) {
            case 16384000:  ff   = (const float*)d_in[i]; break;
            case 327680:    rec  = (const float*)d_in[i]; break;
            case 104857600: wab  = (const float*)d_in[i]; break;
            case 67108864:  wstp = (const float*)d_in[i]; break;
            default: break;
        }
    }
    if (!ff || !rec || !wab || !wstp) {
        ff   = (const float*)d_in[0];
        rec  = (const float*)d_in[1];
        wab  = (const float*)d_in[2];
        wstp = (const float*)d_in[3];
    }
    float* out = (float*)d_out;

    k_zero<<<(NN * 5 * 8 + 255) / 256, 256>>>();
    {
        long long tot = (long long)NN * NN / 4;
        k_fill_wab<<<(unsigned)((tot + 255) / 256), 256>>>(wab);
    }
    {
        long long tot = (long long)NE * NE / 4;
        k_fill_wstp<<<(unsigned)((tot + 255) / 256), 256>>>(wstp);
    }
    k_pad<<<(NN * 5 * 8 + 255) / 256, 256>>>();
    k_init<<<(NN * BB + 255) / 256, 256>>>(ff, rec);

    const size_t shmem = 2 * (size_t)REGSZ + (size_t)NPBMAX * 32 * sizeof(float);
    static int smem_set = 0;
    if (!smem_set) {
        cudaFuncSetAttribute(k_run, cudaFuncAttributeMaxDynamicSharedMemorySize,
                             (int)shmem);
        smem_set = 1;
    }

    int dev = 0;
    cudaGetDevice(&dev);
    int sms = 0;
    cudaDeviceGetAttribute(&sms, cudaDevAttrMultiProcessorCount, dev);
    if (sms <= 0) sms = 148;
    int nblk = sms;
    int eblk = (int)(((long long)nblk * NE + NN / 2) / NN);
    if (eblk < 1) eblk = 1;
    if (eblk > nblk - 1) eblk = nblk - 1;
    while ((NE + eblk - 1) / eblk > NPBMAX) ++eblk;
    k_run<<<nblk, NTHR, shmem>>>(ff, out, nblk, eblk);
}